// round 15
// baseline (speedup 1.0000x reference)
#include <cuda_runtime.h>
#include <cuda_fp16.h>
#include <cstdint>
#include <cstddef>

// Problem constants
#define BB 8
#define TT 2048
#define HH 1024
#define MM (BB*TT)        // 16384
#define NHOP 12
#define THRESH 0.9f
#define LNEPS 1e-5f

// 1-term fp16 GEMM: A=hi(base) [MM x 1024], B=hi(Wt) [HH x 1024].
// Ac scaling + rank-12 term applied exactly in fp32 epilogue.
#define K2   1024
#define KT   64              // fp16 per k-tile
#define NT   (K2 / KT)       // 16

// -------- device scratch (static, no runtime allocation) --------
__device__ __half g_Asplit[(size_t)MM * K2];   // 33.6 MB
__device__ __half g_Bsplit[(size_t)HH * K2];   // 2.1 MB
__device__ float g_c[NHOP * HH];               // c_k[o] (fp32)
__device__ float g_w[(size_t)MM * NHOP];       // per-token hop weights
__device__ float g_Ac[MM];                     // per-token A-scale
__device__ float g_gw[HH];                     // gamma*wp
__device__ float g_spk[NHOP];
__device__ float g_mupos[NHOP];
__device__ float g_qpos[NHOP];
__device__ float g_C0;
__device__ float g_G;
__device__ unsigned g_flag;                    // const-ready flag (reset via memsetAsync)

// ======================= helpers =======================
__device__ __forceinline__ uint32_t smem_u32(const void* p) {
    uint32_t a;
    asm("{ .reg .u64 t; cvta.to.shared.u64 t, %1; cvt.u32.u64 %0, t; }" : "=r"(a) : "l"(p));
    return a;
}

__device__ __forceinline__ void cp16(uint32_t dst, const void* src) {
    asm volatile("cp.async.cg.shared.global [%0], [%1], 16;" :: "r"(dst), "l"(src));
}
#define CP_COMMIT() asm volatile("cp.async.commit_group;" ::: "memory")

#define LDSM4(R, addr) \
    asm volatile("ldmatrix.sync.aligned.m8n8.x4.shared.b16 {%0,%1,%2,%3}, [%4];" \
        : "=r"((R)[0]), "=r"((R)[1]), "=r"((R)[2]), "=r"((R)[3]) : "r"(addr))

#define MMA16816(C, A, b0, b1) \
    asm volatile("mma.sync.aligned.m16n8k16.row.col.f32.f16.f16.f32 " \
        "{%0,%1,%2,%3}, {%4,%5,%6,%7}, {%8,%9}, {%0,%1,%2,%3};" \
        : "+f"((C)[0]), "+f"((C)[1]), "+f"((C)[2]), "+f"((C)[3]) \
        : "r"((A)[0]), "r"((A)[1]), "r"((A)[2]), "r"((A)[3]), "r"(b0), "r"(b1))

__device__ __forceinline__ float warpReduce(float v) {
    #pragma unroll
    for (int o = 16; o > 0; o >>= 1) v += __shfl_xor_sync(0xffffffffu, v, o);
    return v;
}
__device__ __forceinline__ float dot4(float4 a, float4 b) {
    return a.x*b.x + a.y*b.y + a.z*b.z + a.w*b.w;
}

// ============ kernel 1 (fully merged) ============
// blocks [0,1024): splitB row o + g_c (blocks 0..12 ALSO compute scalar constants, release flag)
// blocks [1024,3072): stats warp-per-token, single pass (A=hi(base) written during stats)
#define DYN_SMEM (NHOP * HH * 4 + 384)   // 49536 B

__global__ __launch_bounds__(256)
void main_kernel(const float* __restrict__ inp,
                 const float* __restrict__ tenc,
                 const float* __restrict__ pos,
                 const float* __restrict__ Wt,
                 const float* __restrict__ bt,
                 const float* __restrict__ gamma,
                 const float* __restrict__ beta,
                 const float* __restrict__ wp,
                 const float* __restrict__ bp,
                 float* __restrict__ out_rem,
                 float* __restrict__ out_nup) {
    extern __shared__ float dyn[];
    const int tid = threadIdx.x;
    const int lane = tid & 31, wid = tid >> 5;

    if (blockIdx.x < 1024) {
        // ---------------- splitB block (+ const duty for bid < 13) ----------------
        const int o = blockIdx.x;

        if (o < NHOP + 1) {
            float* red2 = dyn + 256;
            if (o < NHOP) {
                float sp = 0.f, mp = 0.f, qp = 0.f;
                for (int h = tid; h < HH; h += 256) {
                    float pv = pos[o*HH + h];
                    sp += pv * gamma[h] * wp[h];
                    mp += pv;
                    qp += pv * pv;
                }
                sp = warpReduce(sp); mp = warpReduce(mp); qp = warpReduce(qp);
                if (lane == 0) { red2[0*8+wid] = sp; red2[1*8+wid] = mp; red2[2*8+wid] = qp; }
                __syncthreads();
                if (tid == 0) {
                    float s = 0.f, m = 0.f, q = 0.f;
                    #pragma unroll
                    for (int i = 0; i < 8; i++) { s += red2[0*8+i]; m += red2[1*8+i]; q += red2[2*8+i]; }
                    g_spk[o] = s;
                    g_mupos[o] = m * (1.f / HH);
                    g_qpos[o] = q * (1.f / HH);
                    __threadfence();
                    atomicAdd(&g_flag, 1u);
                }
            } else {  // o == NHOP: gw / C0 / G
                float c0 = 0.f, g = 0.f;
                for (int h = tid; h < HH; h += 256) {
                    float gw = gamma[h] * wp[h];
                    g_gw[h] = gw;
                    c0 += beta[h] * wp[h];
                    g  += gw;
                }
                c0 = warpReduce(c0); g = warpReduce(g);
                if (lane == 0) { red2[0*8+wid] = c0; red2[1*8+wid] = g; }
                __syncthreads();
                if (tid == 0) {
                    float s = 0.f, s2 = 0.f;
                    #pragma unroll
                    for (int i = 0; i < 8; i++) { s += red2[0*8+i]; s2 += red2[1*8+i]; }
                    g_C0 = s + bp[0];
                    g_G = s2;
                    __threadfence();
                    atomicAdd(&g_flag, 1u);
                }
            }
            __syncthreads();
        }

        // splitB row o: B = hi(Wt[o]); c_k[o] = pos_k . Wt[o] + bt[o]
        __half* dst = g_Bsplit + (size_t)o * K2;
        float4 v = ((const float4*)(Wt + (size_t)o * HH))[tid];
        {
            __half hi[4];
            hi[0] = __float2half_rn(v.x);
            hi[1] = __float2half_rn(v.y);
            hi[2] = __float2half_rn(v.z);
            hi[3] = __float2half_rn(v.w);
            *(uint2*)(dst + 4*tid) = *(uint2*)hi;
        }

        const float4* p4 = (const float4*)pos;
        float acc[NHOP];
        #pragma unroll
        for (int k = 0; k < NHOP; k++)
            acc[k] = dot4(v, p4[k*(HH/4) + tid]);

        float* red = dyn;            // [12][8]
        #pragma unroll
        for (int k = 0; k < NHOP; k++) {
            float r = warpReduce(acc[k]);
            if (lane == 0) red[k*8 + wid] = r;
        }
        __syncthreads();
        if (tid < NHOP) {
            float s = 0.f;
            #pragma unroll
            for (int i = 0; i < 8; i++) s += red[tid*8 + i];
            g_c[tid*HH + o] = s + bt[o];
        }
        return;
    }

    // ---------------- stats block (single pass) ----------------
    // stage pos into smem
    {
        float4* pd = (float4*)dyn;
        const float4* ps = (const float4*)pos;
        #pragma unroll
        for (int i = 0; i < 12; i++)
            pd[tid + i * 256] = ps[tid + i * 256];
    }
    __syncthreads();

    const int m = (blockIdx.x - 1024) * 8 + wid;
    const float4* in4 = (const float4*)inp + (size_t)m * (HH/4);
    const float4* t4p = (const float4*)tenc + (size_t)(m & (TT-1)) * (HH/4);
    const float4* gw4 = (const float4*)g_gw;
    const float4* p4s = (const float4*)dyn;   // staged pos

    // single pass: stats + unscaled A write
    __half* dst = g_Asplit + (size_t)m * K2;
    float s0 = 0.f, s1 = 0.f, s2 = 0.f;
    float sp[NHOP];
    #pragma unroll
    for (int k = 0; k < NHOP; k++) sp[k] = 0.f;
    #pragma unroll
    for (int seg = 0; seg < 8; seg++) {
        float4 a = in4[seg*32 + lane];
        float4 t = t4p[seg*32 + lane];
        float4 b = make_float4(a.x+t.x, a.y+t.y, a.z+t.z, a.w+t.w);
        {
            __half hi[4];
            hi[0] = __float2half_rn(b.x);
            hi[1] = __float2half_rn(b.y);
            hi[2] = __float2half_rn(b.z);
            hi[3] = __float2half_rn(b.w);
            *(uint2*)(dst + seg*128 + lane*4) = *(uint2*)hi;
        }
        s0 += b.x + b.y + b.z + b.w;
        s1 += dot4(b, b);
        s2 += dot4(b, gw4[seg*32 + lane]);
        #pragma unroll
        for (int k = 0; k < NHOP; k++)
            sp[k] += dot4(b, p4s[k*(HH/4) + seg*32 + lane]);
    }

    s0 = warpReduce(s0); s1 = warpReduce(s1); s2 = warpReduce(s2);
    #pragma unroll
    for (int k = 0; k < NHOP; k++) sp[k] = warpReduce(sp[k]);

    // acquire-wait: constants ready (13 releases) — all lanes spin (converged)
    {
        unsigned f;
        do {
            asm volatile("ld.acquire.gpu.global.u32 %0, [%1];" : "=r"(f) : "l"(&g_flag) : "memory");
            if (f >= NHOP + 1) break;
            __nanosleep(64);
        } while (true);
    }

    const float mu_b = s0 * (1.f / HH);
    const float q_b  = s1 * (1.f / HH);
    const float G = g_G, C0 = g_C0;

    float hp = 0.f, rem = 0.f, nup = 0.f;
    float uw[NHOP];
    #pragma unroll
    for (int k = 0; k < NHOP; k++) {
        float mu  = mu_b + g_mupos[k];
        float ex2 = q_b + 2.f * sp[k] * (1.f / HH) + g_qpos[k];
        float var = ex2 - mu * mu;
        float Sg  = s2 + g_spk[k];
        float logit = rsqrtf(var + LNEPS) * (Sg - mu * G) + C0;
        float p = 1.f / (1.f + expf(-logit));

        float sr  = (hp < 1.f) ? 1.f : 0.f;
        float acc = hp + p * sr;
        float nh  = (acc > THRESH) ? sr : 0.f;
        sr        = (acc <= THRESH) ? sr : 0.f;
        hp  = hp + p * sr;
        rem = rem + nh * (1.f - hp);
        hp  = hp + nh * rem;
        nup = nup + sr + nh;
        uw[k] = p * sr + nh * rem;
    }
    float wv[NHOP];
    float prod = 1.f, Ac = 0.f;
    #pragma unroll
    for (int k = NHOP-1; k >= 0; k--) {
        float wk = uw[k] * prod;
        wv[k] = wk;
        Ac += wk;
        prod *= (1.f - uw[k]);
    }
    if (lane == 0) {
        out_rem[m] = rem;
        out_nup[m] = nup;
        g_Ac[m] = Ac;
        float* wd = g_w + (size_t)m * NHOP;
        *(float4*)(wd)     = make_float4(wv[0], wv[1], wv[2], wv[3]);
        *(float4*)(wd + 4) = make_float4(wv[4], wv[5], wv[6], wv[7]);
        *(float4*)(wd + 8) = make_float4(wv[8], wv[9], wv[10], wv[11]);
    }
}

// ======================= kernel 2: fp16 mma.sync GEMM + fp32 epilogue =======================
// 128x128 CTA tile, 256 threads, warp grid 2(M) x 4(N), warp tile 64x32,
// 3-stage cp.async pipeline, 2 CTAs/SM.
// Epilogue: out = Ac[m]*acc + sum_k w[m,k]*c[k,n]   (exact fp32)

#define TM 128
#define TN 128
#define ROWB 144                        // padded row bytes: 64 fp16 = 128B + 16B pad
#define ABYTES (TM * ROWB)              // 18432
#define BBYTES (TN * ROWB)              // 18432
#define STAGEB (ABYTES + BBYTES)        // 36864
#define NSTAGE 3
#define SMEM_GEMM (NSTAGE * STAGEB)     // 110592

__device__ __forceinline__ void load_tiles(uint32_t sa, int stage, int kt, int bm, int bn, int tid) {
    const __half* Ab = g_Asplit + (size_t)bm * K2 + kt * KT;
    uint32_t adst = sa + stage * STAGEB;
    #pragma unroll
    for (int i = 0; i < 4; i++) {
        int id = tid + i * 256;
        int row = id >> 3, cc = id & 7;
        cp16(adst + row * ROWB + cc * 16, Ab + (size_t)row * K2 + cc * 8);
    }
    const __half* Bb = g_Bsplit + (size_t)bn * K2 + kt * KT;
    uint32_t bdst = sa + stage * STAGEB + ABYTES;
    #pragma unroll
    for (int i = 0; i < 4; i++) {
        int id = tid + i * 256;
        int row = id >> 3, cc = id & 7;
        cp16(bdst + row * ROWB + cc * 16, Bb + (size_t)row * K2 + cc * 8);
    }
}

__global__ __launch_bounds__(256, 2)
void gemm_mma_kernel(float* __restrict__ outp) {
    extern __shared__ char smem[];
    uint32_t sa = smem_u32(smem);
    const int tid = threadIdx.x;
    const int lane = tid & 31;
    const int warp = tid >> 5;
    const int wm = (warp & 1) * 64;    // 2 warps along M (64 rows each)
    const int wn = (warp >> 1) * 32;   // 4 warps along N (32 cols each)
    const int bm = blockIdx.y * TM;
    const int bn = blockIdx.x * TN;

    const int g = lane >> 3, r = lane & 7;
    const uint32_t a_lm = sa + (uint32_t)((wm + (g & 1) * 8 + r) * ROWB + (g >> 1) * 16);
    const uint32_t b_lm = sa + ABYTES + (uint32_t)((wn + (g >> 1) * 8 + r) * ROWB + (g & 1) * 16);

    float acc[4][2][8];
    #pragma unroll
    for (int i = 0; i < 4; i++)
        #pragma unroll
        for (int j = 0; j < 2; j++)
            #pragma unroll
            for (int q = 0; q < 8; q++) acc[i][j][q] = 0.f;

    load_tiles(sa, 0, 0, bm, bn, tid);
    CP_COMMIT();
    load_tiles(sa, 1, 1, bm, bn, tid);
    CP_COMMIT();

    int stage = 0;
    for (int kt = 0; kt < NT; kt++) {
        asm volatile("cp.async.wait_group 1;" ::: "memory");
        __syncthreads();

        if (kt + 2 < NT) {
            int nstage = stage + 2; if (nstage >= NSTAGE) nstage -= NSTAGE;
            load_tiles(sa, nstage, kt + 2, bm, bn, tid);
        }
        CP_COMMIT();

        const uint32_t abuf = a_lm + stage * STAGEB;
        const uint32_t bbuf = b_lm + stage * STAGEB;

        #pragma unroll
        for (int ks = 0; ks < 4; ks++) {
            uint32_t af[4][4];
            #pragma unroll
            for (int mf = 0; mf < 4; mf++)
                LDSM4(af[mf], abuf + mf * (16 * ROWB) + ks * 32);
            uint32_t bfr[2][4];
            #pragma unroll
            for (int nf = 0; nf < 2; nf++)
                LDSM4(bfr[nf], bbuf + nf * (16 * ROWB) + ks * 32);
            #pragma unroll
            for (int mf = 0; mf < 4; mf++)
                #pragma unroll
                for (int nf = 0; nf < 2; nf++) {
                    MMA16816(acc[mf][nf] + 0, af[mf], bfr[nf][0], bfr[nf][1]);
                    MMA16816(acc[mf][nf] + 4, af[mf], bfr[nf][2], bfr[nf][3]);
                }
        }
        stage++; if (stage >= NSTAGE) stage = 0;
    }

    // ---- epilogue: Ac scale + exact rank-12 ----
    __syncthreads();   // mainloop smem no longer needed
    float* c_sm = (float*)smem;              // [12][128]
    float* w_sm = c_sm + NHOP * TN;          // [128][12]
    float* a_sm = w_sm + TM * NHOP;          // [128]
    for (int i = tid; i < NHOP * TN; i += 256) {
        int k = i >> 7, j = i & 127;
        c_sm[i] = g_c[k * HH + bn + j];
    }
    for (int i = tid; i < TM * NHOP; i += 256) {
        int row = i / NHOP, k = i - row * NHOP;
        w_sm[i] = g_w[(size_t)(bm + row) * NHOP + k];
    }
    if (tid < TM) a_sm[tid] = g_Ac[bm + tid];
    __syncthreads();

    const int rA0 = wm + (lane >> 2);          // local row (mf adds 16)
    const int cL0 = wn + (lane & 3) * 2;       // local col (nf adds 16)

    // Ac scaling
    #pragma unroll
    for (int mf = 0; mf < 4; mf++) {
        const int ra = rA0 + mf * 16;
        const float AcA = a_sm[ra];
        const float AcB = a_sm[ra + 8];
        #pragma unroll
        for (int nf = 0; nf < 2; nf++) {
            acc[mf][nf][0] *= AcA; acc[mf][nf][1] *= AcA;
            acc[mf][nf][4] *= AcA; acc[mf][nf][5] *= AcA;
            acc[mf][nf][2] *= AcB; acc[mf][nf][3] *= AcB;
            acc[mf][nf][6] *= AcB; acc[mf][nf][7] *= AcB;
        }
    }

    // rank-12 add
    #pragma unroll
    for (int k = 0; k < NHOP; k++) {
        float cv[2][4];
        #pragma unroll
        for (int nf = 0; nf < 2; nf++) {
            const int c0 = cL0 + nf * 16;
            cv[nf][0] = c_sm[k * TN + c0];
            cv[nf][1] = c_sm[k * TN + c0 + 1];
            cv[nf][2] = c_sm[k * TN + c0 + 8];
            cv[nf][3] = c_sm[k * TN + c0 + 9];
        }
        #pragma unroll
        for (int mf = 0; mf < 4; mf++) {
            const int ra = rA0 + mf * 16;
            const float wA = w_sm[ra * NHOP + k];
            const float wB = w_sm[(ra + 8) * NHOP + k];
            #pragma unroll
            for (int nf = 0; nf < 2; nf++) {
                acc[mf][nf][0] += wA * cv[nf][0];
                acc[mf][nf][1] += wA * cv[nf][1];
                acc[mf][nf][2] += wB * cv[nf][0];
                acc[mf][nf][3] += wB * cv[nf][1];
                acc[mf][nf][4] += wA * cv[nf][2];
                acc[mf][nf][5] += wA * cv[nf][3];
                acc[mf][nf][6] += wB * cv[nf][2];
                acc[mf][nf][7] += wB * cv[nf][3];
            }
        }
    }

    // store
    #pragma unroll
    for (int mf = 0; mf < 4; mf++) {
        #pragma unroll
        for (int nf = 0; nf < 2; nf++) {
            const int row0 = bm + wm + mf * 16 + (lane >> 2);
            const int col0 = bn + wn + nf * 16 + (lane & 3) * 2;
            float* p = outp + (size_t)row0 * HH + col0;
            *(float2*)(p)              = make_float2(acc[mf][nf][0], acc[mf][nf][1]);
            *(float2*)(p + 8*HH)       = make_float2(acc[mf][nf][2], acc[mf][nf][3]);
            *(float2*)(p + 8)          = make_float2(acc[mf][nf][4], acc[mf][nf][5]);
            *(float2*)(p + 8*HH + 8)   = make_float2(acc[mf][nf][6], acc[mf][nf][7]);
        }
    }
}

// ======================= host launch =======================
extern "C" void kernel_launch(void* const* d_in, const int* in_sizes, int n_in,
                              void* d_out, int out_size) {
    const float* inp   = (const float*)d_in[0];
    const float* tenc  = (const float*)d_in[1];
    const float* pos   = (const float*)d_in[2];
    const float* gamma = (const float*)d_in[3];
    const float* beta  = (const float*)d_in[4];
    const float* wp    = (const float*)d_in[5];
    const float* bp    = (const float*)d_in[6];
    const float* Wt    = (const float*)d_in[7];
    const float* bt    = (const float*)d_in[8];

    float* outp    = (float*)d_out;
    float* out_rem = outp + (size_t)MM * HH;
    float* out_nup = out_rem + MM;

    cudaFuncSetAttribute(main_kernel, cudaFuncAttributeMaxDynamicSharedMemorySize, DYN_SMEM);
    cudaFuncSetAttribute(gemm_mma_kernel, cudaFuncAttributeMaxDynamicSharedMemorySize, SMEM_GEMM);

    void* flag_addr = nullptr;
    cudaGetSymbolAddress(&flag_addr, g_flag);
    cudaMemsetAsync(flag_addr, 0, sizeof(unsigned), 0);   // reset release flag (graph-legal)

    main_kernel<<<1024 + 2048, 256, DYN_SMEM>>>(inp, tenc, pos, Wt, bt,
                                                gamma, beta, wp, bp, out_rem, out_nup);
    gemm_mma_kernel<<<dim3(HH / TN, MM / TM), 256, SMEM_GEMM>>>(outp);
}

// round 16
// speedup vs baseline: 1.0209x; 1.0209x over previous
#include <cuda_runtime.h>
#include <cuda_fp16.h>
#include <cstdint>
#include <cstddef>

// Problem constants
#define BB 8
#define TT 2048
#define HH 1024
#define MM (BB*TT)        // 16384
#define NHOP 12
#define THRESH 0.9f
#define LNEPS 1e-5f

// 1-term fp16 GEMM: A=hi(base) [unscaled] + 64 ext cols carrying (w/Ac) splits.
// Whole accumulator scaled by Ac[m] in a featherweight epilogue.
#define KSPL 1024
#define KEXT 64
#define K2   (KSPL + KEXT)   // 1088
#define KT   64              // fp16 per k-tile
#define NT   (K2 / KT)       // 17

// -------- device scratch (static, no runtime allocation) --------
__device__ __half g_Asplit[(size_t)MM * K2];   // ~35.7 MB
__device__ __half g_Bsplit[(size_t)HH * K2];   // ~2.2 MB
__device__ float g_Ac[MM];                     // per-token scale
__device__ float g_gw[HH];                     // gamma*wp
__device__ float g_spk[NHOP];
__device__ float g_mupos[NHOP];
__device__ float g_qpos[NHOP];
__device__ float g_C0;
__device__ float g_G;
__device__ unsigned g_flag;                    // const-ready flag (reset via memsetAsync)

// ======================= helpers =======================
__device__ __forceinline__ uint32_t smem_u32(const void* p) {
    uint32_t a;
    asm("{ .reg .u64 t; cvta.to.shared.u64 t, %1; cvt.u32.u64 %0, t; }" : "=r"(a) : "l"(p));
    return a;
}

__device__ __forceinline__ void cp16(uint32_t dst, const void* src) {
    asm volatile("cp.async.cg.shared.global [%0], [%1], 16;" :: "r"(dst), "l"(src));
}
#define CP_COMMIT() asm volatile("cp.async.commit_group;" ::: "memory")

#define LDSM4(R, addr) \
    asm volatile("ldmatrix.sync.aligned.m8n8.x4.shared.b16 {%0,%1,%2,%3}, [%4];" \
        : "=r"((R)[0]), "=r"((R)[1]), "=r"((R)[2]), "=r"((R)[3]) : "r"(addr))

#define MMA16816(C, A, b0, b1) \
    asm volatile("mma.sync.aligned.m16n8k16.row.col.f32.f16.f16.f32 " \
        "{%0,%1,%2,%3}, {%4,%5,%6,%7}, {%8,%9}, {%0,%1,%2,%3};" \
        : "+f"((C)[0]), "+f"((C)[1]), "+f"((C)[2]), "+f"((C)[3]) \
        : "r"((A)[0]), "r"((A)[1]), "r"((A)[2]), "r"((A)[3]), "r"(b0), "r"(b1))

__device__ __forceinline__ float warpReduce(float v) {
    #pragma unroll
    for (int o = 16; o > 0; o >>= 1) v += __shfl_xor_sync(0xffffffffu, v, o);
    return v;
}
__device__ __forceinline__ float dot4(float4 a, float4 b) {
    return a.x*b.x + a.y*b.y + a.z*b.z + a.w*b.w;
}

// ============ kernel 1 (fully merged) ============
// blocks [0,1024): splitB row o (blocks 0..12 ALSO compute scalar constants, release flag)
// blocks [1024,3072): stats warp-per-token, SINGLE pass (A=hi(base) written during stats)
#define DYN_SMEM (NHOP * HH * 4 + 384)   // 49536 B

__global__ __launch_bounds__(256)
void main_kernel(const float* __restrict__ inp,
                 const float* __restrict__ tenc,
                 const float* __restrict__ pos,
                 const float* __restrict__ Wt,
                 const float* __restrict__ bt,
                 const float* __restrict__ gamma,
                 const float* __restrict__ beta,
                 const float* __restrict__ wp,
                 const float* __restrict__ bp,
                 float* __restrict__ out_rem,
                 float* __restrict__ out_nup) {
    extern __shared__ float dyn[];
    const int tid = threadIdx.x;
    const int lane = tid & 31, wid = tid >> 5;

    if (blockIdx.x < 1024) {
        // ---------------- splitB block (+ const duty for bid < 13) ----------------
        const int o = blockIdx.x;

        if (o < NHOP + 1) {
            float* red2 = dyn + 256;
            if (o < NHOP) {
                float sp = 0.f, mp = 0.f, qp = 0.f;
                for (int h = tid; h < HH; h += 256) {
                    float pv = pos[o*HH + h];
                    sp += pv * gamma[h] * wp[h];
                    mp += pv;
                    qp += pv * pv;
                }
                sp = warpReduce(sp); mp = warpReduce(mp); qp = warpReduce(qp);
                if (lane == 0) { red2[0*8+wid] = sp; red2[1*8+wid] = mp; red2[2*8+wid] = qp; }
                __syncthreads();
                if (tid == 0) {
                    float s = 0.f, m = 0.f, q = 0.f;
                    #pragma unroll
                    for (int i = 0; i < 8; i++) { s += red2[0*8+i]; m += red2[1*8+i]; q += red2[2*8+i]; }
                    g_spk[o] = s;
                    g_mupos[o] = m * (1.f / HH);
                    g_qpos[o] = q * (1.f / HH);
                    __threadfence();
                    atomicAdd(&g_flag, 1u);
                }
            } else {  // o == NHOP: gw / C0 / G
                float c0 = 0.f, g = 0.f;
                for (int h = tid; h < HH; h += 256) {
                    float gw = gamma[h] * wp[h];
                    g_gw[h] = gw;
                    c0 += beta[h] * wp[h];
                    g  += gw;
                }
                c0 = warpReduce(c0); g = warpReduce(g);
                if (lane == 0) { red2[0*8+wid] = c0; red2[1*8+wid] = g; }
                __syncthreads();
                if (tid == 0) {
                    float s = 0.f, s2 = 0.f;
                    #pragma unroll
                    for (int i = 0; i < 8; i++) { s += red2[0*8+i]; s2 += red2[1*8+i]; }
                    g_C0 = s + bp[0];
                    g_G = s2;
                    __threadfence();
                    atomicAdd(&g_flag, 1u);
                }
            }
            __syncthreads();
        }

        // splitB row o: B = hi(Wt[o]); ext = c_hi|c_hi|c_lo
        __half* dst = g_Bsplit + (size_t)o * K2;
        float4 v = ((const float4*)(Wt + (size_t)o * HH))[tid];
        {
            __half hi[4];
            hi[0] = __float2half_rn(v.x);
            hi[1] = __float2half_rn(v.y);
            hi[2] = __float2half_rn(v.z);
            hi[3] = __float2half_rn(v.w);
            *(uint2*)(dst + 4*tid) = *(uint2*)hi;
        }

        const float4* p4 = (const float4*)pos;
        float acc[NHOP];
        #pragma unroll
        for (int k = 0; k < NHOP; k++)
            acc[k] = dot4(v, p4[k*(HH/4) + tid]);

        float* red = dyn;            // [12][8]
        float* c_s = dyn + 96;       // [12]
        #pragma unroll
        for (int k = 0; k < NHOP; k++) {
            float r = warpReduce(acc[k]);
            if (lane == 0) red[k*8 + wid] = r;
        }
        __syncthreads();
        if (tid < NHOP) {
            float s = 0.f;
            #pragma unroll
            for (int i = 0; i < 8; i++) s += red[tid*8 + i];
            c_s[tid] = s + bt[o];
        }
        __syncthreads();

        if (tid < KEXT) {
            __half val = __float2half_rn(0.f);
            if (tid < 24) {
                int k = (tid < 12) ? tid : tid - 12;
                val = __float2half_rn(c_s[k]);
            } else if (tid < 36) {
                float c = c_s[tid-24];
                __half h = __float2half_rn(c);
                val = __float2half_rn(c - __half2float(h));
            }
            dst[KSPL + tid] = val;
        }
        return;
    }

    // ---------------- stats block (single pass) ----------------
    // stage pos into smem
    {
        float4* pd = (float4*)dyn;
        const float4* ps = (const float4*)pos;
        #pragma unroll
        for (int i = 0; i < 12; i++)
            pd[tid + i * 256] = ps[tid + i * 256];
    }
    __syncthreads();

    const int m = (blockIdx.x - 1024) * 8 + wid;
    const float4* in4 = (const float4*)inp + (size_t)m * (HH/4);
    const float4* t4p = (const float4*)tenc + (size_t)(m & (TT-1)) * (HH/4);
    const float4* gw4 = (const float4*)g_gw;
    const float4* p4s = (const float4*)dyn;   // staged pos

    // single pass: stats + UNSCALED A write
    __half* dst = g_Asplit + (size_t)m * K2;
    float s0 = 0.f, s1 = 0.f, s2 = 0.f;
    float sp[NHOP];
    #pragma unroll
    for (int k = 0; k < NHOP; k++) sp[k] = 0.f;
    #pragma unroll
    for (int seg = 0; seg < 8; seg++) {
        float4 a = in4[seg*32 + lane];
        float4 t = t4p[seg*32 + lane];
        float4 b = make_float4(a.x+t.x, a.y+t.y, a.z+t.z, a.w+t.w);
        {
            __half hi[4];
            hi[0] = __float2half_rn(b.x);
            hi[1] = __float2half_rn(b.y);
            hi[2] = __float2half_rn(b.z);
            hi[3] = __float2half_rn(b.w);
            *(uint2*)(dst + seg*128 + lane*4) = *(uint2*)hi;
        }
        s0 += b.x + b.y + b.z + b.w;
        s1 += dot4(b, b);
        s2 += dot4(b, gw4[seg*32 + lane]);
        #pragma unroll
        for (int k = 0; k < NHOP; k++)
            sp[k] += dot4(b, p4s[k*(HH/4) + seg*32 + lane]);
    }

    s0 = warpReduce(s0); s1 = warpReduce(s1); s2 = warpReduce(s2);
    #pragma unroll
    for (int k = 0; k < NHOP; k++) sp[k] = warpReduce(sp[k]);

    // acquire-wait: constants ready (13 releases) — converged across warp
    {
        unsigned f;
        do {
            asm volatile("ld.acquire.gpu.global.u32 %0, [%1];" : "=r"(f) : "l"(&g_flag) : "memory");
            if (f >= NHOP + 1) break;
            __nanosleep(64);
        } while (true);
    }

    const float mu_b = s0 * (1.f / HH);
    const float q_b  = s1 * (1.f / HH);
    const float G = g_G, C0 = g_C0;

    float hp = 0.f, rem = 0.f, nup = 0.f;
    float uw[NHOP];
    #pragma unroll
    for (int k = 0; k < NHOP; k++) {
        float mu  = mu_b + g_mupos[k];
        float ex2 = q_b + 2.f * sp[k] * (1.f / HH) + g_qpos[k];
        float var = ex2 - mu * mu;
        float Sg  = s2 + g_spk[k];
        float logit = rsqrtf(var + LNEPS) * (Sg - mu * G) + C0;
        float p = 1.f / (1.f + expf(-logit));

        float sr  = (hp < 1.f) ? 1.f : 0.f;
        float acc = hp + p * sr;
        float nh  = (acc > THRESH) ? sr : 0.f;
        sr        = (acc <= THRESH) ? sr : 0.f;
        hp  = hp + p * sr;
        rem = rem + nh * (1.f - hp);
        hp  = hp + nh * rem;
        nup = nup + sr + nh;
        uw[k] = p * sr + nh * rem;
    }
    float wv[NHOP];
    float prod = 1.f, Ac = 0.f;
    #pragma unroll
    for (int k = NHOP-1; k >= 0; k--) {
        float wk = uw[k] * prod;
        wv[k] = wk;
        Ac += wk;
        prod *= (1.f - uw[k]);
    }
    if (lane == 0) { out_rem[m] = rem; out_nup[m] = nup; g_Ac[m] = Ac; }

    // ext: 2 entries per lane, storing (wv/Ac) splits so the epilogue's global
    // Ac multiply reconstructs wv exactly: Ac*(wv/Ac) = wv.
    {
        const float inv = 1.f / Ac;
        __half v0 = __float2half_rn(0.f), v1 = __float2half_rn(0.f);
        int j = lane;
        if (j < 12) {
            v0 = __float2half_rn(wv[j] * inv);
        } else if (j < 24) {
            float w = wv[j-12] * inv;
            __half h = __float2half_rn(w);
            v0 = __float2half_rn(w - __half2float(h));
        } else {
            v0 = __float2half_rn(wv[j-24] * inv);
        }
        int j2 = lane + 32;
        if (j2 < 36) v1 = __float2half_rn(wv[j2-24] * inv);
        dst[KSPL + j]  = v0;
        dst[KSPL + j2] = v1;
    }
}

// ======================= kernel 2: fp16 mma.sync GEMM + Ac-scale epilogue =======================
// 128x128 CTA tile, 256 threads, warp grid 2(M) x 4(N), warp tile 64x32,
// 3-stage cp.async pipeline, 2 CTAs/SM. Epilogue: acc *= Ac[row] (featherweight).

#define TM 128
#define TN 128
#define ROWB 144                        // padded row bytes: 64 fp16 = 128B + 16B pad
#define ABYTES (TM * ROWB)              // 18432
#define BBYTES (TN * ROWB)              // 18432
#define STAGEB (ABYTES + BBYTES)        // 36864
#define NSTAGE 3
#define SMEM_GEMM (NSTAGE * STAGEB)     // 110592

__device__ __forceinline__ void load_tiles(uint32_t sa, int stage, int kt, int bm, int bn, int tid) {
    const __half* Ab = g_Asplit + (size_t)bm * K2 + kt * KT;
    uint32_t adst = sa + stage * STAGEB;
    #pragma unroll
    for (int i = 0; i < 4; i++) {
        int id = tid + i * 256;
        int row = id >> 3, cc = id & 7;
        cp16(adst + row * ROWB + cc * 16, Ab + (size_t)row * K2 + cc * 8);
    }
    const __half* Bb = g_Bsplit + (size_t)bn * K2 + kt * KT;
    uint32_t bdst = sa + stage * STAGEB + ABYTES;
    #pragma unroll
    for (int i = 0; i < 4; i++) {
        int id = tid + i * 256;
        int row = id >> 3, cc = id & 7;
        cp16(bdst + row * ROWB + cc * 16, Bb + (size_t)row * K2 + cc * 8);
    }
}

__global__ __launch_bounds__(256, 2)
void gemm_mma_kernel(float* __restrict__ outp) {
    extern __shared__ char smem[];
    uint32_t sa = smem_u32(smem);
    const int tid = threadIdx.x;
    const int lane = tid & 31;
    const int warp = tid >> 5;
    const int wm = (warp & 1) * 64;    // 2 warps along M (64 rows each)
    const int wn = (warp >> 1) * 32;   // 4 warps along N (32 cols each)
    const int bm = blockIdx.y * TM;
    const int bn = blockIdx.x * TN;

    const int g = lane >> 3, r = lane & 7;
    const uint32_t a_lm = sa + (uint32_t)((wm + (g & 1) * 8 + r) * ROWB + (g >> 1) * 16);
    const uint32_t b_lm = sa + ABYTES + (uint32_t)((wn + (g >> 1) * 8 + r) * ROWB + (g & 1) * 16);

    float acc[4][2][8];
    #pragma unroll
    for (int i = 0; i < 4; i++)
        #pragma unroll
        for (int j = 0; j < 2; j++)
            #pragma unroll
            for (int q = 0; q < 8; q++) acc[i][j][q] = 0.f;

    load_tiles(sa, 0, 0, bm, bn, tid);
    CP_COMMIT();
    load_tiles(sa, 1, 1, bm, bn, tid);
    CP_COMMIT();

    int stage = 0;
    for (int kt = 0; kt < NT; kt++) {
        asm volatile("cp.async.wait_group 1;" ::: "memory");
        __syncthreads();

        if (kt + 2 < NT) {
            int nstage = stage + 2; if (nstage >= NSTAGE) nstage -= NSTAGE;
            load_tiles(sa, nstage, kt + 2, bm, bn, tid);
        }
        CP_COMMIT();

        const uint32_t abuf = a_lm + stage * STAGEB;
        const uint32_t bbuf = b_lm + stage * STAGEB;

        #pragma unroll
        for (int ks = 0; ks < 4; ks++) {
            uint32_t af[4][4];
            #pragma unroll
            for (int mf = 0; mf < 4; mf++)
                LDSM4(af[mf], abuf + mf * (16 * ROWB) + ks * 32);
            uint32_t bfr[2][4];
            #pragma unroll
            for (int nf = 0; nf < 2; nf++)
                LDSM4(bfr[nf], bbuf + nf * (16 * ROWB) + ks * 32);
            #pragma unroll
            for (int mf = 0; mf < 4; mf++)
                #pragma unroll
                for (int nf = 0; nf < 2; nf++) {
                    MMA16816(acc[mf][nf] + 0, af[mf], bfr[nf][0], bfr[nf][1]);
                    MMA16816(acc[mf][nf] + 4, af[mf], bfr[nf][2], bfr[nf][3]);
                }
        }
        stage++; if (stage >= NSTAGE) stage = 0;
    }

    // featherweight epilogue: stage Ac[128] and scale during store
    __syncthreads();
    float* a_sm = (float*)smem;
    if (tid < TM) a_sm[tid] = g_Ac[bm + tid];
    __syncthreads();

    #pragma unroll
    for (int mf = 0; mf < 4; mf++) {
        const int rloc = wm + mf * 16 + (lane >> 2);
        const float AcA = a_sm[rloc];
        const float AcB = a_sm[rloc + 8];
        #pragma unroll
        for (int nf = 0; nf < 2; nf++) {
            const int row0 = bm + rloc;
            const int col0 = bn + wn + nf * 16 + (lane & 3) * 2;
            float* p = outp + (size_t)row0 * HH + col0;
            *(float2*)(p)              = make_float2(acc[mf][nf][0]*AcA, acc[mf][nf][1]*AcA);
            *(float2*)(p + 8*HH)       = make_float2(acc[mf][nf][2]*AcB, acc[mf][nf][3]*AcB);
            *(float2*)(p + 8)          = make_float2(acc[mf][nf][4]*AcA, acc[mf][nf][5]*AcA);
            *(float2*)(p + 8*HH + 8)   = make_float2(acc[mf][nf][6]*AcB, acc[mf][nf][7]*AcB);
        }
    }
}

// ======================= host launch =======================
extern "C" void kernel_launch(void* const* d_in, const int* in_sizes, int n_in,
                              void* d_out, int out_size) {
    const float* inp   = (const float*)d_in[0];
    const float* tenc  = (const float*)d_in[1];
    const float* pos   = (const float*)d_in[2];
    const float* gamma = (const float*)d_in[3];
    const float* beta  = (const float*)d_in[4];
    const float* wp    = (const float*)d_in[5];
    const float* bp    = (const float*)d_in[6];
    const float* Wt    = (const float*)d_in[7];
    const float* bt    = (const float*)d_in[8];

    float* outp    = (float*)d_out;
    float* out_rem = outp + (size_t)MM * HH;
    float* out_nup = out_rem + MM;

    cudaFuncSetAttribute(main_kernel, cudaFuncAttributeMaxDynamicSharedMemorySize, DYN_SMEM);
    cudaFuncSetAttribute(gemm_mma_kernel, cudaFuncAttributeMaxDynamicSharedMemorySize, SMEM_GEMM);

    void* flag_addr = nullptr;
    cudaGetSymbolAddress(&flag_addr, g_flag);
    cudaMemsetAsync(flag_addr, 0, sizeof(unsigned), 0);   // reset release flag (graph-legal)

    main_kernel<<<1024 + 2048, 256, DYN_SMEM>>>(inp, tenc, pos, Wt, bt,
                                                gamma, beta, wp, bp, out_rem, out_nup);
    gemm_mma_kernel<<<dim3(HH / TN, MM / TM), 256, SMEM_GEMM>>>(outp);
}

// round 17
// speedup vs baseline: 1.0408x; 1.0195x over previous
#include <cuda_runtime.h>
#include <cuda_fp16.h>
#include <cstdint>
#include <cstddef>

// Problem constants
#define BB 8
#define TT 2048
#define HH 1024
#define MM (BB*TT)        // 16384
#define NHOP 12
#define THRESH 0.9f
#define LNEPS 1e-5f

// 1-term fp16 GEMM: A=hi(base) [unscaled] + 64 ext cols carrying (w/Ac) splits.
// Whole accumulator scaled by Ac[m] in a featherweight epilogue.
#define KSPL 1024
#define KEXT 64
#define K2   (KSPL + KEXT)   // 1088
#define KT   64              // fp16 per k-tile
#define NT   (K2 / KT)       // 17

// -------- device scratch (static, no runtime allocation) --------
__device__ __half g_Asplit[(size_t)MM * K2];   // ~35.7 MB
__device__ __half g_Bsplit[(size_t)HH * K2];   // ~2.2 MB
__device__ float g_Ac[MM];                     // per-token scale
__device__ float g_gw[HH];                     // gamma*wp
__device__ float g_spk[NHOP];
__device__ float g_mupos[NHOP];
__device__ float g_qpos[NHOP];
__device__ float g_C0;
__device__ float g_G;
__device__ unsigned g_flag;                    // const-ready flag (reset via memsetAsync)

// ======================= helpers =======================
__device__ __forceinline__ uint32_t smem_u32(const void* p) {
    uint32_t a;
    asm("{ .reg .u64 t; cvta.to.shared.u64 t, %1; cvt.u32.u64 %0, t; }" : "=r"(a) : "l"(p));
    return a;
}

__device__ __forceinline__ void cp16(uint32_t dst, const void* src) {
    asm volatile("cp.async.cg.shared.global [%0], [%1], 16;" :: "r"(dst), "l"(src));
}
#define CP_COMMIT() asm volatile("cp.async.commit_group;" ::: "memory")

#define LDSM4(R, addr) \
    asm volatile("ldmatrix.sync.aligned.m8n8.x4.shared.b16 {%0,%1,%2,%3}, [%4];" \
        : "=r"((R)[0]), "=r"((R)[1]), "=r"((R)[2]), "=r"((R)[3]) : "r"(addr))

#define MMA16816(C, A, b0, b1) \
    asm volatile("mma.sync.aligned.m16n8k16.row.col.f32.f16.f16.f32 " \
        "{%0,%1,%2,%3}, {%4,%5,%6,%7}, {%8,%9}, {%0,%1,%2,%3};" \
        : "+f"((C)[0]), "+f"((C)[1]), "+f"((C)[2]), "+f"((C)[3]) \
        : "r"((A)[0]), "r"((A)[1]), "r"((A)[2]), "r"((A)[3]), "r"(b0), "r"(b1))

__device__ __forceinline__ float warpReduce(float v) {
    #pragma unroll
    for (int o = 16; o > 0; o >>= 1) v += __shfl_xor_sync(0xffffffffu, v, o);
    return v;
}
__device__ __forceinline__ float dot4(float4 a, float4 b) {
    return a.x*b.x + a.y*b.y + a.z*b.z + a.w*b.w;
}

// ============ kernel 1 (fully merged) ============
// blocks [0,1024): splitB row o (blocks 0..12 ALSO compute scalar constants, release flag)
// blocks [1024,3072): stats warp-per-token, SINGLE pass (A=hi(base) written during stats)
// pos hops 0..9 staged in smem (40KB -> 5 CTAs/SM); hops 10,11 read from L2.
#define SHOPS 10
#define DYN_SMEM (SHOPS * HH * 4 + 384)   // 41344 B

__global__ __launch_bounds__(256)
void main_kernel(const float* __restrict__ inp,
                 const float* __restrict__ tenc,
                 const float* __restrict__ pos,
                 const float* __restrict__ Wt,
                 const float* __restrict__ bt,
                 const float* __restrict__ gamma,
                 const float* __restrict__ beta,
                 const float* __restrict__ wp,
                 const float* __restrict__ bp,
                 float* __restrict__ out_rem,
                 float* __restrict__ out_nup) {
    extern __shared__ float dyn[];
    const int tid = threadIdx.x;
    const int lane = tid & 31, wid = tid >> 5;

    if (blockIdx.x < 1024) {
        // ---------------- splitB block (+ const duty for bid < 13) ----------------
        const int o = blockIdx.x;

        if (o < NHOP + 1) {
            float* red2 = dyn + 256;
            if (o < NHOP) {
                float sp = 0.f, mp = 0.f, qp = 0.f;
                for (int h = tid; h < HH; h += 256) {
                    float pv = pos[o*HH + h];
                    sp += pv * gamma[h] * wp[h];
                    mp += pv;
                    qp += pv * pv;
                }
                sp = warpReduce(sp); mp = warpReduce(mp); qp = warpReduce(qp);
                if (lane == 0) { red2[0*8+wid] = sp; red2[1*8+wid] = mp; red2[2*8+wid] = qp; }
                __syncthreads();
                if (tid == 0) {
                    float s = 0.f, m = 0.f, q = 0.f;
                    #pragma unroll
                    for (int i = 0; i < 8; i++) { s += red2[0*8+i]; m += red2[1*8+i]; q += red2[2*8+i]; }
                    g_spk[o] = s;
                    g_mupos[o] = m * (1.f / HH);
                    g_qpos[o] = q * (1.f / HH);
                    __threadfence();
                    atomicAdd(&g_flag, 1u);
                }
            } else {  // o == NHOP: gw / C0 / G
                float c0 = 0.f, g = 0.f;
                for (int h = tid; h < HH; h += 256) {
                    float gw = gamma[h] * wp[h];
                    g_gw[h] = gw;
                    c0 += beta[h] * wp[h];
                    g  += gw;
                }
                c0 = warpReduce(c0); g = warpReduce(g);
                if (lane == 0) { red2[0*8+wid] = c0; red2[1*8+wid] = g; }
                __syncthreads();
                if (tid == 0) {
                    float s = 0.f, s2 = 0.f;
                    #pragma unroll
                    for (int i = 0; i < 8; i++) { s += red2[0*8+i]; s2 += red2[1*8+i]; }
                    g_C0 = s + bp[0];
                    g_G = s2;
                    __threadfence();
                    atomicAdd(&g_flag, 1u);
                }
            }
            __syncthreads();
        }

        // splitB row o: B = hi(Wt[o]); ext = c_hi|c_hi|c_lo
        __half* dst = g_Bsplit + (size_t)o * K2;
        float4 v = ((const float4*)(Wt + (size_t)o * HH))[tid];
        {
            __half hi[4];
            hi[0] = __float2half_rn(v.x);
            hi[1] = __float2half_rn(v.y);
            hi[2] = __float2half_rn(v.z);
            hi[3] = __float2half_rn(v.w);
            *(uint2*)(dst + 4*tid) = *(uint2*)hi;
        }

        const float4* p4 = (const float4*)pos;
        float acc[NHOP];
        #pragma unroll
        for (int k = 0; k < NHOP; k++)
            acc[k] = dot4(v, p4[k*(HH/4) + tid]);

        float* red = dyn;            // [12][8]
        float* c_s = dyn + 96;       // [12]
        #pragma unroll
        for (int k = 0; k < NHOP; k++) {
            float r = warpReduce(acc[k]);
            if (lane == 0) red[k*8 + wid] = r;
        }
        __syncthreads();
        if (tid < NHOP) {
            float s = 0.f;
            #pragma unroll
            for (int i = 0; i < 8; i++) s += red[tid*8 + i];
            c_s[tid] = s + bt[o];
        }
        __syncthreads();

        if (tid < KEXT) {
            __half val = __float2half_rn(0.f);
            if (tid < 24) {
                int k = (tid < 12) ? tid : tid - 12;
                val = __float2half_rn(c_s[k]);
            } else if (tid < 36) {
                float c = c_s[tid-24];
                __half h = __float2half_rn(c);
                val = __float2half_rn(c - __half2float(h));
            }
            dst[KSPL + tid] = val;
        }
        return;
    }

    // ---------------- stats block (single pass) ----------------
    // stage pos hops 0..SHOPS-1 into smem: SHOPS*256 float4
    {
        float4* pd = (float4*)dyn;
        const float4* ps = (const float4*)pos;
        #pragma unroll
        for (int i = 0; i < SHOPS; i++)
            pd[tid + i * 256] = ps[tid + i * 256];
    }
    __syncthreads();

    const int m = (blockIdx.x - 1024) * 8 + wid;
    const float4* in4 = (const float4*)inp + (size_t)m * (HH/4);
    const float4* t4p = (const float4*)tenc + (size_t)(m & (TT-1)) * (HH/4);
    const float4* gw4 = (const float4*)g_gw;
    const float4* p4s = (const float4*)dyn;   // staged pos (hops 0..9)
    const float4* p4g = (const float4*)pos;   // global pos (hops 10,11)

    // single pass: stats + UNSCALED A write
    __half* dst = g_Asplit + (size_t)m * K2;
    float s0 = 0.f, s1 = 0.f, s2 = 0.f;
    float sp[NHOP];
    #pragma unroll
    for (int k = 0; k < NHOP; k++) sp[k] = 0.f;
    #pragma unroll
    for (int seg = 0; seg < 8; seg++) {
        float4 a = in4[seg*32 + lane];
        float4 t = t4p[seg*32 + lane];
        float4 b = make_float4(a.x+t.x, a.y+t.y, a.z+t.z, a.w+t.w);
        {
            __half hi[4];
            hi[0] = __float2half_rn(b.x);
            hi[1] = __float2half_rn(b.y);
            hi[2] = __float2half_rn(b.z);
            hi[3] = __float2half_rn(b.w);
            *(uint2*)(dst + seg*128 + lane*4) = *(uint2*)hi;
        }
        s0 += b.x + b.y + b.z + b.w;
        s1 += dot4(b, b);
        s2 += dot4(b, gw4[seg*32 + lane]);
        #pragma unroll
        for (int k = 0; k < SHOPS; k++)
            sp[k] += dot4(b, p4s[k*(HH/4) + seg*32 + lane]);
        #pragma unroll
        for (int k = SHOPS; k < NHOP; k++)
            sp[k] += dot4(b, p4g[k*(HH/4) + seg*32 + lane]);
    }

    s0 = warpReduce(s0); s1 = warpReduce(s1); s2 = warpReduce(s2);
    #pragma unroll
    for (int k = 0; k < NHOP; k++) sp[k] = warpReduce(sp[k]);

    // acquire-wait: constants ready (13 releases) — converged across warp
    {
        unsigned f;
        do {
            asm volatile("ld.acquire.gpu.global.u32 %0, [%1];" : "=r"(f) : "l"(&g_flag) : "memory");
            if (f >= NHOP + 1) break;
            __nanosleep(64);
        } while (true);
    }

    const float mu_b = s0 * (1.f / HH);
    const float q_b  = s1 * (1.f / HH);
    const float G = g_G, C0 = g_C0;

    float hp = 0.f, rem = 0.f, nup = 0.f;
    float uw[NHOP];
    #pragma unroll
    for (int k = 0; k < NHOP; k++) {
        float mu  = mu_b + g_mupos[k];
        float ex2 = q_b + 2.f * sp[k] * (1.f / HH) + g_qpos[k];
        float var = ex2 - mu * mu;
        float Sg  = s2 + g_spk[k];
        float logit = rsqrtf(var + LNEPS) * (Sg - mu * G) + C0;
        float p = 1.f / (1.f + expf(-logit));

        float sr  = (hp < 1.f) ? 1.f : 0.f;
        float acc = hp + p * sr;
        float nh  = (acc > THRESH) ? sr : 0.f;
        sr        = (acc <= THRESH) ? sr : 0.f;
        hp  = hp + p * sr;
        rem = rem + nh * (1.f - hp);
        hp  = hp + nh * rem;
        nup = nup + sr + nh;
        uw[k] = p * sr + nh * rem;
    }
    float wv[NHOP];
    float prod = 1.f, Ac = 0.f;
    #pragma unroll
    for (int k = NHOP-1; k >= 0; k--) {
        float wk = uw[k] * prod;
        wv[k] = wk;
        Ac += wk;
        prod *= (1.f - uw[k]);
    }
    if (lane == 0) { out_rem[m] = rem; out_nup[m] = nup; g_Ac[m] = Ac; }

    // ext: 2 entries per lane, storing (wv/Ac) splits so the epilogue's global
    // Ac multiply reconstructs wv exactly: Ac*(wv/Ac) = wv.
    {
        const float inv = 1.f / Ac;
        __half v0 = __float2half_rn(0.f), v1 = __float2half_rn(0.f);
        int j = lane;
        if (j < 12) {
            v0 = __float2half_rn(wv[j] * inv);
        } else if (j < 24) {
            float w = wv[j-12] * inv;
            __half h = __float2half_rn(w);
            v0 = __float2half_rn(w - __half2float(h));
        } else {
            v0 = __float2half_rn(wv[j-24] * inv);
        }
        int j2 = lane + 32;
        if (j2 < 36) v1 = __float2half_rn(wv[j2-24] * inv);
        dst[KSPL + j]  = v0;
        dst[KSPL + j2] = v1;
    }
}

// ======================= kernel 2: fp16 mma.sync GEMM + Ac-scale epilogue =======================
// 128x128 CTA tile, 256 threads, warp grid 2(M) x 4(N), warp tile 64x32,
// 3-stage cp.async pipeline, 2 CTAs/SM. Epilogue: acc *= Ac[row] (featherweight).

#define TM 128
#define TN 128
#define ROWB 144                        // padded row bytes: 64 fp16 = 128B + 16B pad
#define ABYTES (TM * ROWB)              // 18432
#define BBYTES (TN * ROWB)              // 18432
#define STAGEB (ABYTES + BBYTES)        // 36864
#define NSTAGE 3
#define SMEM_GEMM (NSTAGE * STAGEB)     // 110592

__device__ __forceinline__ void load_tiles(uint32_t sa, int stage, int kt, int bm, int bn, int tid) {
    const __half* Ab = g_Asplit + (size_t)bm * K2 + kt * KT;
    uint32_t adst = sa + stage * STAGEB;
    #pragma unroll
    for (int i = 0; i < 4; i++) {
        int id = tid + i * 256;
        int row = id >> 3, cc = id & 7;
        cp16(adst + row * ROWB + cc * 16, Ab + (size_t)row * K2 + cc * 8);
    }
    const __half* Bb = g_Bsplit + (size_t)bn * K2 + kt * KT;
    uint32_t bdst = sa + stage * STAGEB + ABYTES;
    #pragma unroll
    for (int i = 0; i < 4; i++) {
        int id = tid + i * 256;
        int row = id >> 3, cc = id & 7;
        cp16(bdst + row * ROWB + cc * 16, Bb + (size_t)row * K2 + cc * 8);
    }
}

__global__ __launch_bounds__(256, 2)
void gemm_mma_kernel(float* __restrict__ outp) {
    extern __shared__ char smem[];
    uint32_t sa = smem_u32(smem);
    const int tid = threadIdx.x;
    const int lane = tid & 31;
    const int warp = tid >> 5;
    const int wm = (warp & 1) * 64;    // 2 warps along M (64 rows each)
    const int wn = (warp >> 1) * 32;   // 4 warps along N (32 cols each)
    const int bm = blockIdx.y * TM;
    const int bn = blockIdx.x * TN;

    const int g = lane >> 3, r = lane & 7;
    const uint32_t a_lm = sa + (uint32_t)((wm + (g & 1) * 8 + r) * ROWB + (g >> 1) * 16);
    const uint32_t b_lm = sa + ABYTES + (uint32_t)((wn + (g >> 1) * 8 + r) * ROWB + (g & 1) * 16);

    float acc[4][2][8];
    #pragma unroll
    for (int i = 0; i < 4; i++)
        #pragma unroll
        for (int j = 0; j < 2; j++)
            #pragma unroll
            for (int q = 0; q < 8; q++) acc[i][j][q] = 0.f;

    load_tiles(sa, 0, 0, bm, bn, tid);
    CP_COMMIT();
    load_tiles(sa, 1, 1, bm, bn, tid);
    CP_COMMIT();

    int stage = 0;
    for (int kt = 0; kt < NT; kt++) {
        asm volatile("cp.async.wait_group 1;" ::: "memory");
        __syncthreads();

        if (kt + 2 < NT) {
            int nstage = stage + 2; if (nstage >= NSTAGE) nstage -= NSTAGE;
            load_tiles(sa, nstage, kt + 2, bm, bn, tid);
        }
        CP_COMMIT();

        const uint32_t abuf = a_lm + stage * STAGEB;
        const uint32_t bbuf = b_lm + stage * STAGEB;

        #pragma unroll
        for (int ks = 0; ks < 4; ks++) {
            uint32_t af[4][4];
            #pragma unroll
            for (int mf = 0; mf < 4; mf++)
                LDSM4(af[mf], abuf + mf * (16 * ROWB) + ks * 32);
            uint32_t bfr[2][4];
            #pragma unroll
            for (int nf = 0; nf < 2; nf++)
                LDSM4(bfr[nf], bbuf + nf * (16 * ROWB) + ks * 32);
            #pragma unroll
            for (int mf = 0; mf < 4; mf++)
                #pragma unroll
                for (int nf = 0; nf < 2; nf++) {
                    MMA16816(acc[mf][nf] + 0, af[mf], bfr[nf][0], bfr[nf][1]);
                    MMA16816(acc[mf][nf] + 4, af[mf], bfr[nf][2], bfr[nf][3]);
                }
        }
        stage++; if (stage >= NSTAGE) stage = 0;
    }

    // featherweight epilogue: stage Ac[128] and scale during store
    __syncthreads();
    float* a_sm = (float*)smem;
    if (tid < TM) a_sm[tid] = g_Ac[bm + tid];
    __syncthreads();

    #pragma unroll
    for (int mf = 0; mf < 4; mf++) {
        const int rloc = wm + mf * 16 + (lane >> 2);
        const float AcA = a_sm[rloc];
        const float AcB = a_sm[rloc + 8];
        #pragma unroll
        for (int nf = 0; nf < 2; nf++) {
            const int row0 = bm + rloc;
            const int col0 = bn + wn + nf * 16 + (lane & 3) * 2;
            float* p = outp + (size_t)row0 * HH + col0;
            *(float2*)(p)              = make_float2(acc[mf][nf][0]*AcA, acc[mf][nf][1]*AcA);
            *(float2*)(p + 8*HH)       = make_float2(acc[mf][nf][2]*AcB, acc[mf][nf][3]*AcB);
            *(float2*)(p + 8)          = make_float2(acc[mf][nf][4]*AcA, acc[mf][nf][5]*AcA);
            *(float2*)(p + 8*HH + 8)   = make_float2(acc[mf][nf][6]*AcB, acc[mf][nf][7]*AcB);
        }
    }
}

// ======================= host launch =======================
extern "C" void kernel_launch(void* const* d_in, const int* in_sizes, int n_in,
                              void* d_out, int out_size) {
    const float* inp   = (const float*)d_in[0];
    const float* tenc  = (const float*)d_in[1];
    const float* pos   = (const float*)d_in[2];
    const float* gamma = (const float*)d_in[3];
    const float* beta  = (const float*)d_in[4];
    const float* wp    = (const float*)d_in[5];
    const float* bp    = (const float*)d_in[6];
    const float* Wt    = (const float*)d_in[7];
    const float* bt    = (const float*)d_in[8];

    float* outp    = (float*)d_out;
    float* out_rem = outp + (size_t)MM * HH;
    float* out_nup = out_rem + MM;

    cudaFuncSetAttribute(main_kernel, cudaFuncAttributeMaxDynamicSharedMemorySize, DYN_SMEM);
    cudaFuncSetAttribute(gemm_mma_kernel, cudaFuncAttributeMaxDynamicSharedMemorySize, SMEM_GEMM);

    void* flag_addr = nullptr;
    cudaGetSymbolAddress(&flag_addr, g_flag);
    cudaMemsetAsync(flag_addr, 0, sizeof(unsigned), 0);   // reset release flag (graph-legal)

    main_kernel<<<1024 + 2048, 256, DYN_SMEM>>>(inp, tenc, pos, Wt, bt,
                                                gamma, beta, wp, bp, out_rem, out_nup);
    gemm_mma_kernel<<<dim3(HH / TN, MM / TM), 256, SMEM_GEMM>>>(outp);
}